// round 14
// baseline (speedup 1.0000x reference)
#include <cuda_runtime.h>

// ---------------------------------------------------------------------------
// Fully-fused 2-layer GAT attention. 512 CTAs x 256 threads, 4 CTAs/SM.
//   exp(leaky_relu(q+k)) = Fq * Ek * max(e^{0.99q}, e^{-0.99k}); Fq cancels.
//   X <- Ek*X;  ATT[i] = sum_j max(Hq,Gk)*EkX / sum_j max(Hq,Gk)*Ek
// R13 base + L1::evict_last on ALL weight loads (pin the 64KB weight set in
// the 69KB L1D carveout; emb streams stay evict-first via .cs).
//   A1: x -> EkX1 -> av1 -> EkX2   A2: Ek   A3: Gk -> ATT
// ---------------------------------------------------------------------------

#define TPB 256
typedef unsigned long long u64;

constexpr int Bn = 512, Nn = 50, Dn = 64;
constexpr int ASZ = Nn * Dn;                  // 3200
constexpr int EMB_STRIDE = (Nn + 1) * Dn;     // 3264

constexpr float L2E   = 1.4426950408889634f;  // log2(e)
constexpr float L2E99 = 0.99f * L2E;

// shared layout (floats)
constexpr int O_A1  = 0;          // x / EkX1 / av1 / EkX2
constexpr int O_A2  = ASZ;        // Ek (per layer)
constexpr int O_A3  = 2 * ASZ;    // Gk -> ATT (per layer)
constexpr int O_BA1 = 3 * ASZ;
constexpr int O_BA2 = O_BA1 + Dn;
constexpr int O_B1  = O_BA2 + Dn;
constexpr int O_B2  = O_B1 + Dn;
constexpr int O_E0  = O_B2 + Dn;
constexpr int SMEM_FLOATS = O_E0 + Dn;        // 9920 floats = 39680 B

// k-pair-packed GEMM weights: g_wp[m][kp][c] = (W_m[2kp][c], W_m[2kp+1][c])
__device__ __align__(16) u64 g_wp[2][32][64];

// ---- f32x2 helpers --------------------------------------------------------
__device__ __forceinline__ u64 pk2(float lo, float hi) {
    u64 r; asm("mov.b64 %0, {%1,%2};" : "=l"(r) : "f"(lo), "f"(hi)); return r;
}
__device__ __forceinline__ u64 dup2(float x) {
    u64 r; asm("mov.b64 %0, {%1,%1};" : "=l"(r) : "f"(x)); return r;
}
__device__ __forceinline__ float lo32(u64 v) {
    float a, b; asm("mov.b64 {%0,%1}, %2;" : "=f"(a), "=f"(b) : "l"(v)); return a;
}
__device__ __forceinline__ float hi32(u64 v) {
    float a, b; asm("mov.b64 {%0,%1}, %2;" : "=f"(a), "=f"(b) : "l"(v)); return b;
}
__device__ __forceinline__ u64 fma2(u64 a, u64 b, u64 c) {
    u64 d; asm("fma.rn.f32x2 %0, %1, %2, %3;" : "=l"(d) : "l"(a), "l"(b), "l"(c)); return d;
}
__device__ __forceinline__ u64 mul2(u64 a, u64 b) {
    u64 d; asm("mul.rn.f32x2 %0, %1, %2;" : "=l"(d) : "l"(a), "l"(b)); return d;
}

// ---- weight loads: read-only + L1 evict_last (pin in L1D) ------------------
__device__ __forceinline__ u64 ldw64(const u64* p) {
    u64 v;
    asm("ld.global.nc.L1::evict_last.b64 %0, [%1];" : "=l"(v) : "l"(p));
    return v;
}
__device__ __forceinline__ ulonglong2 ldw128(const ulonglong2* p) {
    ulonglong2 v;
    asm("ld.global.nc.L1::evict_last.v2.b64 {%0,%1}, [%2];"
        : "=l"(v.x), "=l"(v.y) : "l"(p));
    return v;
}

// ---- streaming (evict-first) global loads: single-use emb data -------------
__device__ __forceinline__ float4 ldcs4(const float4* p) {
    float4 v;
    asm("ld.global.cs.v4.f32 {%0,%1,%2,%3}, [%4];"
        : "=f"(v.x), "=f"(v.y), "=f"(v.z), "=f"(v.w) : "l"(p));
    return v;
}
__device__ __forceinline__ float2 ldcs2(const float2* p) {
    float2 v;
    asm("ld.global.cs.v2.f32 {%0,%1}, [%2];" : "=f"(v.x), "=f"(v.y) : "l"(p));
    return v;
}

// ---- prepack: W1, W2 -> k-pair-interleaved u64 form -------------------------
__global__ void prepack_kernel(const float* __restrict__ W1,
                               const float* __restrict__ W2) {
    const int idx = blockIdx.x * blockDim.x + threadIdx.x;   // 0..4095
    const int m  = idx >> 11;
    const int r  = idx & 2047;
    const int kp = r >> 6;
    const int c  = r & 63;
    const float* W = (m == 0) ? W1 : W2;
    g_wp[m][kp][c] = pk2(W[(2 * kp) * Dn + c], W[(2 * kp + 1) * Dn + c]);
}

// ---- qk (R rows): q,k proj -> hq regs, Ek->A2, Gk->A3; then A1 <- Ek*A1 ----
template <int R>
__device__ __forceinline__ void qk_phase(float* sm, const float* __restrict__ Wa1,
                                         const float* __restrict__ Wa2,
                                         float* hq0, float* hq1, int w, int lane) {
    const int d2 = lane * 2;

    u64 aq[R], ak[R];
    const u64 bq = *reinterpret_cast<const u64*>(sm + O_BA1 + d2);
    const u64 bk = *reinterpret_cast<const u64*>(sm + O_BA2 + d2);
#pragma unroll
    for (int r = 0; r < R; ++r) { aq[r] = bq; ak[r] = bk; }

#pragma unroll 2
    for (int c0 = 0; c0 < Dn; c0 += 2) {
        u64 x2[R];
#pragma unroll
        for (int r = 0; r < R; ++r)
            x2[r] = *reinterpret_cast<const u64*>(sm + O_A1 + (w + 8 * r) * Dn + c0);
#pragma unroll
        for (int u = 0; u < 2; ++u) {
            const u64 wa = ldw64(reinterpret_cast<const u64*>(Wa1 + (c0 + u) * Dn) + lane);
            const u64 wb = ldw64(reinterpret_cast<const u64*>(Wa2 + (c0 + u) * Dn) + lane);
#pragma unroll
            for (int r = 0; r < R; ++r) {
                const u64 xx = dup2(u ? hi32(x2[r]) : lo32(x2[r]));
                aq[r] = fma2(xx, wa, aq[r]);
                ak[r] = fma2(xx, wb, ak[r]);
            }
        }
    }

    u64 ekr[R];
#pragma unroll
    for (int r = 0; r < R; ++r) {
        const int row = w + 8 * r;
        const float qa = lo32(aq[r]), qb = hi32(aq[r]);
        const float ka = lo32(ak[r]), kb = hi32(ak[r]);
        hq0[r] = exp2f(qa * L2E99);              // Hq stays in registers
        hq1[r] = exp2f(qb * L2E99);
        const float e0 = exp2f(ka * L2E), e1 = exp2f(kb * L2E);
        ekr[r] = pk2(e0, e1);
        *reinterpret_cast<u64*>(sm + O_A2 + row * Dn + d2) = ekr[r];          // Ek
        *reinterpret_cast<u64*>(sm + O_A3 + row * Dn + d2) =
            pk2(exp2f(ka * -L2E99), exp2f(kb * -L2E99));                      // Gk
    }
    __syncwarp();   // rows warp-private: only intra-warp hazard on A1
#pragma unroll
    for (int r = 0; r < R; ++r) {
        u64* px = reinterpret_cast<u64*>(sm + O_A1 + (w + 8 * r) * Dn + d2);
        *px = mul2(ekr[r], *px);   // A1 <- Ek * A1
    }
}

// ---- attention accumulate (R rows): num/den over j --------------------------
template <int R>
__device__ __forceinline__ void att_acc(const float* __restrict__ sm,
                                        const float* hq0, const float* hq1,
                                        int lane, u64* num, u64* den) {
    const int d2 = lane * 2;
#pragma unroll
    for (int r = 0; r < R; ++r) { num[r] = 0ull; den[r] = 0ull; }

#pragma unroll 2
    for (int j = 0; j < Nn; ++j) {
        const u64 gk2 = *reinterpret_cast<const u64*>(sm + O_A3 + j * Dn + d2);
        const u64 ek  = *reinterpret_cast<const u64*>(sm + O_A2 + j * Dn + d2);
        const u64 xw  = *reinterpret_cast<const u64*>(sm + O_A1 + j * Dn + d2);
        const float gk0 = lo32(gk2), gk1 = hi32(gk2);   // unpack once per j
#pragma unroll
        for (int r = 0; r < R; ++r) {
            const u64 m = pk2(fmaxf(hq0[r], gk0), fmaxf(hq1[r], gk1));
            den[r] = fma2(m, ek, den[r]);
            num[r] = fma2(m, xw, num[r]);
        }
    }
}

// ---- attention store (R rows): ATT -> A3 (over dead Gk, post-barrier) ------
template <int R>
__device__ __forceinline__ void att_store(float* sm, const u64* num,
                                          const u64* den, int w, int lane) {
    const int d2 = lane * 2;
#pragma unroll
    for (int r = 0; r < R; ++r) {
        *reinterpret_cast<u64*>(sm + O_A3 + (w + 8 * r) * Dn + d2) =
            pk2(__fdividef(lo32(num[r]), lo32(den[r])),
                __fdividef(hi32(num[r]), hi32(den[r])));
    }
}

// ---- gemm (R rows): A3(ATT) @ W + b. !FINAL -> A1 (av1). FINAL -> gmem -----
template <int R, bool FINAL>
__device__ __forceinline__ void gemm_phase(float* sm, const u64* __restrict__ wp,
                                           int bofs, const float* __restrict__ emb,
                                           float* __restrict__ out, int b,
                                           int w, int lane) {
    const int d2 = lane * 2;

    // Prefetch final-epilogue globals before the FMA loop (overlap LDG).
    float ui0[FINAL ? R : 1], ui1[FINAL ? R : 1];
    if (FINAL) {
        const float e0a = sm[O_E0 + d2], e0b = sm[O_E0 + d2 + 1];
#pragma unroll
        for (int r = 0; r < R; ++r) {
            const float2 ie = ldcs2(reinterpret_cast<const float2*>(
                emb + b * EMB_STRIDE + (w + 8 * r + 1) * Dn + d2));
            ui0[r] = e0a * ie.x;
            ui1[r] = e0b * ie.y;
        }
    }

    u64 a0[R], a1[R];
#pragma unroll
    for (int r = 0; r < R; ++r) { a0[r] = 0ull; a1[r] = 0ull; }
#pragma unroll 2
    for (int kq = 0; kq < 16; ++kq) {
        const ulonglong2 w0 = ldw128(reinterpret_cast<const ulonglong2*>(wp + (2 * kq) * Dn) + lane);
        const ulonglong2 w1 = ldw128(reinterpret_cast<const ulonglong2*>(wp + (2 * kq + 1) * Dn) + lane);
#pragma unroll
        for (int r = 0; r < R; ++r) {
            const ulonglong2 xv = *reinterpret_cast<const ulonglong2*>(
                sm + O_A3 + (w + 8 * r) * Dn + 4 * kq);
            a0[r] = fma2(xv.x, w0.x, a0[r]);
            a1[r] = fma2(xv.x, w0.y, a1[r]);
            a0[r] = fma2(xv.y, w1.x, a0[r]);
            a1[r] = fma2(xv.y, w1.y, a1[r]);
        }
    }

    const float b0 = sm[bofs + d2], b1 = sm[bofs + d2 + 1];
#pragma unroll
    for (int r = 0; r < R; ++r) {
        const int row = w + 8 * r;
        const float t0 = lo32(a0[r]) + hi32(a0[r]) + b0;
        const float t1 = lo32(a1[r]) + hi32(a1[r]) + b1;
        if (!FINAL) {
            *reinterpret_cast<u64*>(sm + O_A1 + row * Dn + d2) = pk2(t0, t1);  // av1
        } else {
            const u64 ekx = *reinterpret_cast<const u64*>(sm + O_A1 + row * Dn + d2);
            const u64 ek  = *reinterpret_cast<const u64*>(sm + O_A2 + row * Dn + d2);
            const float av0 = __fdividef(lo32(ekx), lo32(ek));   // av1 = EkX2/Ek2
            const float av1 = __fdividef(hi32(ekx), hi32(ek));
            float r0 = t0 + av0 + ui0[r];
            float r1 = t1 + av1 + ui1[r];
            r0 = fmaxf(r0, 0.01f * r0);
            r1 = fmaxf(r1, 0.01f * r1);
            *reinterpret_cast<float2*>(out + b * ASZ + row * Dn + d2) =
                make_float2(r0, r1);
        }
    }
}

__global__ void __launch_bounds__(TPB, 4)
att0_fused_kernel(const float* __restrict__ emb,
                  const float* __restrict__ Wa1, const float* __restrict__ ba1,
                  const float* __restrict__ Wa2, const float* __restrict__ ba2,
                  const float* __restrict__ b1,  const float* __restrict__ b2,
                  float* __restrict__ out) {
    extern __shared__ float sm[];
    const int b = blockIdx.x, tid = threadIdx.x;
    const int lane = tid & 31, w = tid >> 5;
    const bool tall = (w < 2);        // warps 0,1 own 7 rows; warps 2-7 own 6
    const float* __restrict__ eb = emb + b * EMB_STRIDE;

    // Streaming load of x (single-use; keep out of L1).
    for (int idx = tid; idx < ASZ / 4; idx += TPB)
        reinterpret_cast<float4*>(sm + O_A1)[idx] =
            ldcs4(reinterpret_cast<const float4*>(eb + Dn) + idx);
    if (tid < Dn) {
        sm[O_BA1 + tid] = ba1[tid];
        sm[O_BA2 + tid] = ba2[tid];
        sm[O_B1  + tid] = b1[tid];
        sm[O_B2  + tid] = b2[tid];
        sm[O_E0  + tid] = eb[tid];
    }
    __syncthreads();

    float hq0[7], hq1[7];
    u64 num[7], den[7];

    // ---- layer 1 ----
    if (tall) qk_phase<7>(sm, Wa1, Wa2, hq0, hq1, w, lane);
    else      qk_phase<6>(sm, Wa1, Wa2, hq0, hq1, w, lane);
    __syncthreads();
    if (tall) att_acc<7>(sm, hq0, hq1, lane, num, den);
    else      att_acc<6>(sm, hq0, hq1, lane, num, den);
    __syncthreads();                       // all Gk/Ek/EkX reads done
    if (tall) att_store<7>(sm, num, den, w, lane);     // ATT1 over Gk1
    else      att_store<6>(sm, num, den, w, lane);
    __syncwarp();   // own-row store -> own-row read, same warp
    if (tall) gemm_phase<7, false>(sm, &g_wp[0][0][0], O_B1, emb, out, b, w, lane);
    else      gemm_phase<6, false>(sm, &g_wp[0][0][0], O_B1, emb, out, b, w, lane);
    __syncwarp();   // av1 (own rows) -> qk2 reads own rows
    // ---- layer 2 ----
    if (tall) qk_phase<7>(sm, Wa1, Wa2, hq0, hq1, w, lane);
    else      qk_phase<6>(sm, Wa1, Wa2, hq0, hq1, w, lane);
    __syncthreads();
    if (tall) att_acc<7>(sm, hq0, hq1, lane, num, den);
    else      att_acc<6>(sm, hq0, hq1, lane, num, den);
    __syncthreads();
    if (tall) att_store<7>(sm, num, den, w, lane);     // ATT2 over Gk2
    else      att_store<6>(sm, num, den, w, lane);
    __syncwarp();
    if (tall) gemm_phase<7, true>(sm, &g_wp[1][0][0], O_B2, emb, out, b, w, lane);
    else      gemm_phase<6, true>(sm, &g_wp[1][0][0], O_B2, emb, out, b, w, lane);
}

extern "C" void kernel_launch(void* const* d_in, const int* in_sizes, int n_in,
                              void* d_out, int out_size) {
    const float* emb = (const float*)d_in[0];
    const float* Wa1 = (const float*)d_in[1];
    const float* ba1 = (const float*)d_in[2];
    const float* Wa2 = (const float*)d_in[3];
    const float* ba2 = (const float*)d_in[4];
    const float* W1  = (const float*)d_in[5];
    const float* b1  = (const float*)d_in[6];
    const float* W2  = (const float*)d_in[7];
    const float* b2  = (const float*)d_in[8];
    float* out = (float*)d_out;

    prepack_kernel<<<16, 256>>>(W1, W2);

    const size_t smem = SMEM_FLOATS * sizeof(float);   // 39680 B -> 4 CTAs/SM
    cudaFuncSetAttribute(att0_fused_kernel,
                         cudaFuncAttributeMaxDynamicSharedMemorySize, (int)smem);
    att0_fused_kernel<<<Bn, TPB, smem>>>(emb, Wa1, ba1, Wa2, ba2, b1, b2, out);
}

// round 15
// speedup vs baseline: 1.0862x; 1.0862x over previous
#include <cuda_runtime.h>

// ---------------------------------------------------------------------------
// Fully-fused 2-layer GAT attention. 128 CTAs x 1024 threads, 1 CTA/SM.
// Each CTA = 4 groups x 8 warps; group g handles batch 4*bid+g with the
// R11 per-warp structure. Weights (64KB) staged to smem ONCE per CTA and
// shared by all 4 groups; groups sync via named barriers (bar.sync 1+g,256),
// so weight loads are conflict-free LDS (29cyc) instead of L2 LDG (~234cyc).
//   exp(leaky_relu(q+k)) = Fq*Ek*max(e^{.99q}, e^{-.99k}); Fq cancels.
//   X <- Ek*X;  ATT[i] = sum_j max(Hq,Gk)*EkX / sum_j max(Hq,Gk)*Ek
// ---------------------------------------------------------------------------

#define TPB 1024
typedef unsigned long long u64;

constexpr int Bn = 512, Nn = 50, Dn = 64;
constexpr int ASZ = Nn * Dn;                  // 3200
constexpr int EMB_STRIDE = (Nn + 1) * Dn;     // 3264

constexpr float L2E   = 1.4426950408889634f;  // log2(e)
constexpr float L2E99 = 0.99f * L2E;

// ---- shared layout (floats) ------------------------------------------------
// weights first (shared by all groups), then biases, then 4 per-group blocks
constexpr int O_WA1 = 0;                      // raw Wa1 [64][64]
constexpr int O_WA2 = 4096;                   // raw Wa2
constexpr int O_W1P = 8192;                   // k-pair-packed W1 (u64[32][64])
constexpr int O_W2P = 12288;                  // k-pair-packed W2
constexpr int O_BA1 = 16384;
constexpr int O_BA2 = O_BA1 + Dn;
constexpr int O_B1  = O_BA2 + Dn;
constexpr int O_B2  = O_B1 + Dn;
constexpr int G_BASE = O_B2 + Dn;             // 16640
// per-group block: A1(3200) A2(3200) A3(3200) E0(64) = 9664 floats
constexpr int O_A1 = 0, O_A2 = 3200, O_A3 = 6400, O_E0 = 9600;
constexpr int G_SIZE = 9664;
constexpr int SMEM_FLOATS = G_BASE + 4 * G_SIZE;   // 55296 floats = 221184 B

// k-pair-packed GEMM weights in gmem: g_wp[m][kp][c] = (W_m[2kp][c], W_m[2kp+1][c])
__device__ __align__(16) u64 g_wp[2][32][64];

// ---- f32x2 helpers --------------------------------------------------------
__device__ __forceinline__ u64 pk2(float lo, float hi) {
    u64 r; asm("mov.b64 %0, {%1,%2};" : "=l"(r) : "f"(lo), "f"(hi)); return r;
}
__device__ __forceinline__ u64 dup2(float x) {
    u64 r; asm("mov.b64 %0, {%1,%1};" : "=l"(r) : "f"(x)); return r;
}
__device__ __forceinline__ float lo32(u64 v) {
    float a, b; asm("mov.b64 {%0,%1}, %2;" : "=f"(a), "=f"(b) : "l"(v)); return a;
}
__device__ __forceinline__ float hi32(u64 v) {
    float a, b; asm("mov.b64 {%0,%1}, %2;" : "=f"(a), "=f"(b) : "l"(v)); return b;
}
__device__ __forceinline__ u64 fma2(u64 a, u64 b, u64 c) {
    u64 d; asm("fma.rn.f32x2 %0, %1, %2, %3;" : "=l"(d) : "l"(a), "l"(b), "l"(c)); return d;
}
__device__ __forceinline__ u64 mul2(u64 a, u64 b) {
    u64 d; asm("mul.rn.f32x2 %0, %1, %2;" : "=l"(d) : "l"(a), "l"(b)); return d;
}

// streaming loads for single-use emb data
__device__ __forceinline__ float4 ldcs4(const float4* p) {
    float4 v;
    asm("ld.global.cs.v4.f32 {%0,%1,%2,%3}, [%4];"
        : "=f"(v.x), "=f"(v.y), "=f"(v.z), "=f"(v.w) : "l"(p));
    return v;
}
__device__ __forceinline__ float2 ldcs2(const float2* p) {
    float2 v;
    asm("ld.global.cs.v2.f32 {%0,%1}, [%2];" : "=f"(v.x), "=f"(v.y) : "l"(p));
    return v;
}

// group-scoped named barrier (8 warps = 256 threads), ids 1..4
__device__ __forceinline__ void gbar(int id) {
    asm volatile("bar.sync %0, 256;" :: "r"(id) : "memory");
}

// ---- prepack: W1, W2 -> k-pair-interleaved u64 form -------------------------
__global__ void prepack_kernel(const float* __restrict__ W1,
                               const float* __restrict__ W2) {
    const int idx = blockIdx.x * blockDim.x + threadIdx.x;   // 0..4095
    const int m  = idx >> 11;
    const int r  = idx & 2047;
    const int kp = r >> 6;
    const int c  = r & 63;
    const float* W = (m == 0) ? W1 : W2;
    g_wp[m][kp][c] = pk2(W[(2 * kp) * Dn + c], W[(2 * kp + 1) * Dn + c]);
}

// ---- qk (R rows): q,k proj -> hq regs, Ek->A2, Gk->A3; then A1 <- Ek*A1 ----
// Weights read from smem (conflict-free LDS.64).
template <int R>
__device__ __forceinline__ void qk_phase(float* sm, float* gsm,
                                         float* hq0, float* hq1,
                                         int wg, int lane) {
    const int d2 = lane * 2;

    u64 aq[R], ak[R];
    const u64 bq = *reinterpret_cast<const u64*>(sm + O_BA1 + d2);
    const u64 bk = *reinterpret_cast<const u64*>(sm + O_BA2 + d2);
#pragma unroll
    for (int r = 0; r < R; ++r) { aq[r] = bq; ak[r] = bk; }

#pragma unroll 2
    for (int c0 = 0; c0 < Dn; c0 += 2) {
        u64 x2[R];
#pragma unroll
        for (int r = 0; r < R; ++r)
            x2[r] = *reinterpret_cast<const u64*>(gsm + O_A1 + (wg + 8 * r) * Dn + c0);
#pragma unroll
        for (int u = 0; u < 2; ++u) {
            const u64 wa = reinterpret_cast<const u64*>(sm + O_WA1 + (c0 + u) * Dn)[lane];
            const u64 wb = reinterpret_cast<const u64*>(sm + O_WA2 + (c0 + u) * Dn)[lane];
#pragma unroll
            for (int r = 0; r < R; ++r) {
                const u64 xx = dup2(u ? hi32(x2[r]) : lo32(x2[r]));
                aq[r] = fma2(xx, wa, aq[r]);
                ak[r] = fma2(xx, wb, ak[r]);
            }
        }
    }

    u64 ekr[R];
#pragma unroll
    for (int r = 0; r < R; ++r) {
        const int row = wg + 8 * r;
        const float qa = lo32(aq[r]), qb = hi32(aq[r]);
        const float ka = lo32(ak[r]), kb = hi32(ak[r]);
        hq0[r] = exp2f(qa * L2E99);              // Hq stays in registers
        hq1[r] = exp2f(qb * L2E99);
        const float e0 = exp2f(ka * L2E), e1 = exp2f(kb * L2E);
        ekr[r] = pk2(e0, e1);
        *reinterpret_cast<u64*>(gsm + O_A2 + row * Dn + d2) = ekr[r];         // Ek
        *reinterpret_cast<u64*>(gsm + O_A3 + row * Dn + d2) =
            pk2(exp2f(ka * -L2E99), exp2f(kb * -L2E99));                      // Gk
    }
    __syncwarp();   // rows warp-private: only intra-warp hazard on A1
#pragma unroll
    for (int r = 0; r < R; ++r) {
        u64* px = reinterpret_cast<u64*>(gsm + O_A1 + (wg + 8 * r) * Dn + d2);
        *px = mul2(ekr[r], *px);   // A1 <- Ek * A1
    }
}

// ---- attention accumulate (R rows): num/den over j --------------------------
template <int R>
__device__ __forceinline__ void att_acc(const float* __restrict__ gsm,
                                        const float* hq0, const float* hq1,
                                        int lane, u64* num, u64* den) {
    const int d2 = lane * 2;
#pragma unroll
    for (int r = 0; r < R; ++r) { num[r] = 0ull; den[r] = 0ull; }

#pragma unroll 2
    for (int j = 0; j < Nn; ++j) {
        const u64 gk2 = *reinterpret_cast<const u64*>(gsm + O_A3 + j * Dn + d2);
        const u64 ek  = *reinterpret_cast<const u64*>(gsm + O_A2 + j * Dn + d2);
        const u64 xw  = *reinterpret_cast<const u64*>(gsm + O_A1 + j * Dn + d2);
        const float gk0 = lo32(gk2), gk1 = hi32(gk2);   // unpack once per j
#pragma unroll
        for (int r = 0; r < R; ++r) {
            const u64 m = pk2(fmaxf(hq0[r], gk0), fmaxf(hq1[r], gk1));
            den[r] = fma2(m, ek, den[r]);
            num[r] = fma2(m, xw, num[r]);
        }
    }
}

// ---- attention store (R rows): ATT -> A3 (over dead Gk, post-barrier) ------
template <int R>
__device__ __forceinline__ void att_store(float* gsm, const u64* num,
                                          const u64* den, int wg, int lane) {
    const int d2 = lane * 2;
#pragma unroll
    for (int r = 0; r < R; ++r) {
        *reinterpret_cast<u64*>(gsm + O_A3 + (wg + 8 * r) * Dn + d2) =
            pk2(__fdividef(lo32(num[r]), lo32(den[r])),
                __fdividef(hi32(num[r]), hi32(den[r])));
    }
}

// ---- gemm (R rows): A3(ATT) @ W + b. !FINAL -> A1 (av1). FINAL -> gmem -----
// Packed weights read from smem (conflict-free LDS.128).
template <int R, bool FINAL>
__device__ __forceinline__ void gemm_phase(float* sm, float* gsm, int wofs,
                                           int bofs, const float* __restrict__ emb,
                                           float* __restrict__ out, int b,
                                           int wg, int lane) {
    const int d2 = lane * 2;

    // Prefetch final-epilogue globals before the FMA loop (overlap LDG).
    float ui0[FINAL ? R : 1], ui1[FINAL ? R : 1];
    if (FINAL) {
        const float e0a = gsm[O_E0 + d2], e0b = gsm[O_E0 + d2 + 1];
#pragma unroll
        for (int r = 0; r < R; ++r) {
            const float2 ie = ldcs2(reinterpret_cast<const float2*>(
                emb + b * EMB_STRIDE + (wg + 8 * r + 1) * Dn + d2));
            ui0[r] = e0a * ie.x;
            ui1[r] = e0b * ie.y;
        }
    }

    const u64* wp = reinterpret_cast<const u64*>(sm + wofs);
    u64 a0[R], a1[R];
#pragma unroll
    for (int r = 0; r < R; ++r) { a0[r] = 0ull; a1[r] = 0ull; }
#pragma unroll 2
    for (int kq = 0; kq < 16; ++kq) {
        const ulonglong2 w0 = reinterpret_cast<const ulonglong2*>(wp + (2 * kq) * Dn)[lane];
        const ulonglong2 w1 = reinterpret_cast<const ulonglong2*>(wp + (2 * kq + 1) * Dn)[lane];
#pragma unroll
        for (int r = 0; r < R; ++r) {
            const ulonglong2 xv = *reinterpret_cast<const ulonglong2*>(
                gsm + O_A3 + (wg + 8 * r) * Dn + 4 * kq);
            a0[r] = fma2(xv.x, w0.x, a0[r]);
            a1[r] = fma2(xv.x, w0.y, a1[r]);
            a0[r] = fma2(xv.y, w1.x, a0[r]);
            a1[r] = fma2(xv.y, w1.y, a1[r]);
        }
    }

    const float b0 = sm[bofs + d2], b1 = sm[bofs + d2 + 1];
#pragma unroll
    for (int r = 0; r < R; ++r) {
        const int row = wg + 8 * r;
        const float t0 = lo32(a0[r]) + hi32(a0[r]) + b0;
        const float t1 = lo32(a1[r]) + hi32(a1[r]) + b1;
        if (!FINAL) {
            *reinterpret_cast<u64*>(gsm + O_A1 + row * Dn + d2) = pk2(t0, t1);  // av1
        } else {
            const u64 ekx = *reinterpret_cast<const u64*>(gsm + O_A1 + row * Dn + d2);
            const u64 ek  = *reinterpret_cast<const u64*>(gsm + O_A2 + row * Dn + d2);
            const float av0 = __fdividef(lo32(ekx), lo32(ek));   // av1 = EkX2/Ek2
            const float av1 = __fdividef(hi32(ekx), hi32(ek));
            float r0 = t0 + av0 + ui0[r];
            float r1 = t1 + av1 + ui1[r];
            r0 = fmaxf(r0, 0.01f * r0);
            r1 = fmaxf(r1, 0.01f * r1);
            *reinterpret_cast<float2*>(out + b * ASZ + row * Dn + d2) =
                make_float2(r0, r1);
        }
    }
}

__global__ void __launch_bounds__(TPB, 1)
att0_fused_kernel(const float* __restrict__ emb,
                  const float* __restrict__ Wa1, const float* __restrict__ ba1,
                  const float* __restrict__ Wa2, const float* __restrict__ ba2,
                  const float* __restrict__ b1,  const float* __restrict__ b2,
                  float* __restrict__ out) {
    extern __shared__ float sm[];
    const int tid  = threadIdx.x;
    const int lane = tid & 31;
    const int w    = tid >> 5;        // 0..31
    const int g    = w >> 3;          // group 0..3
    const int wg   = w & 7;           // warp-in-group 0..7
    const int b    = blockIdx.x * 4 + g;
    const bool tall = (wg < 2);       // warps 0,1 of group: 7 rows; 2-7: 6
    const int bar  = 1 + g;           // named barrier id per group
    float* gsm = sm + G_BASE + g * G_SIZE;
    const float* __restrict__ eb = emb + b * EMB_STRIDE;

    // ---- stage weights (whole CTA) + per-group x/E0 ----
    {
        const int t = tid;
        if (t < 1024) {
            reinterpret_cast<float4*>(sm + O_WA1)[t] =
                __ldg(reinterpret_cast<const float4*>(Wa1) + t);
            reinterpret_cast<float4*>(sm + O_WA2)[t] =
                __ldg(reinterpret_cast<const float4*>(Wa2) + t);
            reinterpret_cast<ulonglong2*>(sm + O_W1P)[t] =
                __ldg(reinterpret_cast<const ulonglong2*>(&g_wp[0][0][0]) + t);
            reinterpret_cast<ulonglong2*>(sm + O_W2P)[t] =
                __ldg(reinterpret_cast<const ulonglong2*>(&g_wp[1][0][0]) + t);
        }
        if (t < Dn) {
            sm[O_BA1 + t] = ba1[t];
            sm[O_BA2 + t] = ba2[t];
            sm[O_B1  + t] = b1[t];
            sm[O_B2  + t] = b2[t];
        }
    }
    {   // per-group: x plane (800 float4) + E0
        const int gt = tid & 255;     // thread-in-group
        for (int idx = gt; idx < ASZ / 4; idx += 256)
            reinterpret_cast<float4*>(gsm + O_A1)[idx] =
                ldcs4(reinterpret_cast<const float4*>(eb + Dn) + idx);
        if (gt < Dn) gsm[O_E0 + gt] = eb[gt];
    }
    __syncthreads();

    float hq0[7], hq1[7];
    u64 num[7], den[7];

    // ---- layer 1 ----
    if (tall) qk_phase<7>(sm, gsm, hq0, hq1, wg, lane);
    else      qk_phase<6>(sm, gsm, hq0, hq1, wg, lane);
    gbar(bar);
    if (tall) att_acc<7>(gsm, hq0, hq1, lane, num, den);
    else      att_acc<6>(gsm, hq0, hq1, lane, num, den);
    gbar(bar);                               // all Gk/Ek/EkX reads done
    if (tall) att_store<7>(gsm, num, den, wg, lane);    // ATT1 over Gk1
    else      att_store<6>(gsm, num, den, wg, lane);
    __syncwarp();   // own-row store -> own-row read, same warp
    if (tall) gemm_phase<7, false>(sm, gsm, O_W1P, O_B1, emb, out, b, wg, lane);
    else      gemm_phase<6, false>(sm, gsm, O_W1P, O_B1, emb, out, b, wg, lane);
    __syncwarp();   // av1 (own rows) -> qk2 reads own rows
    // ---- layer 2 ----
    if (tall) qk_phase<7>(sm, gsm, hq0, hq1, wg, lane);
    else      qk_phase<6>(sm, gsm, hq0, hq1, wg, lane);
    gbar(bar);
    if (tall) att_acc<7>(gsm, hq0, hq1, lane, num, den);
    else      att_acc<6>(gsm, hq0, hq1, lane, num, den);
    gbar(bar);
    if (tall) att_store<7>(gsm, num, den, wg, lane);    // ATT2 over Gk2
    else      att_store<6>(gsm, num, den, wg, lane);
    __syncwarp();
    if (tall) gemm_phase<7, true>(sm, gsm, O_W2P, O_B2, emb, out, b, wg, lane);
    else      gemm_phase<6, true>(sm, gsm, O_W2P, O_B2, emb, out, b, wg, lane);
}

extern "C" void kernel_launch(void* const* d_in, const int* in_sizes, int n_in,
                              void* d_out, int out_size) {
    const float* emb = (const float*)d_in[0];
    const float* Wa1 = (const float*)d_in[1];
    const float* ba1 = (const float*)d_in[2];
    const float* Wa2 = (const float*)d_in[3];
    const float* ba2 = (const float*)d_in[4];
    const float* W1  = (const float*)d_in[5];
    const float* b1  = (const float*)d_in[6];
    const float* W2  = (const float*)d_in[7];
    const float* b2  = (const float*)d_in[8];
    float* out = (float*)d_out;

    prepack_kernel<<<16, 256>>>(W1, W2);

    const size_t smem = SMEM_FLOATS * sizeof(float);   // 221184 B, 1 CTA/SM
    cudaFuncSetAttribute(att0_fused_kernel,
                         cudaFuncAttributeMaxDynamicSharedMemorySize, (int)smem);
    att0_fused_kernel<<<Bn / 4, TPB, smem>>>(emb, Wa1, ba1, Wa2, ba2, b1, b2, out);
}